// round 13
// baseline (speedup 1.0000x reference)
#include <cuda_runtime.h>
#include <cuda_bf16.h>
#include <math.h>
#include <stdint.h>

#define NN 50000
#define EE 800000

extern __shared__ char dynsm[];

__device__ float g_pre[(size_t)NN * 64 * 4];
__device__ float g_acc[(size_t)NN * 64 * 4];

__device__ __forceinline__ float silu(float x) {
    return x * (1.0f / (1.0f + __expf(-x)));
}

__device__ __forceinline__ uint32_t smem_u32(const void* p) {
    uint32_t a;
    asm("{ .reg .u64 t; cvta.to.shared.u64 t, %1; cvt.u32.u64 %0, t; }"
        : "=r"(a) : "l"(p));
    return a;
}

// split a pair of floats into bf16 hi and lo packed u32s
__device__ __forceinline__ void split2(float a, float b, uint32_t& hi, uint32_t& lo) {
    __nv_bfloat16 ah = __float2bfloat16(a);
    __nv_bfloat16 bh = __float2bfloat16(b);
    __nv_bfloat16 al = __float2bfloat16(a - __bfloat162float(ah));
    __nv_bfloat16 bl = __float2bfloat16(b - __bfloat162float(bh));
    hi = ((uint32_t)__bfloat16_as_ushort(bh) << 16) | (uint32_t)__bfloat16_as_ushort(ah);
    lo = ((uint32_t)__bfloat16_as_ushort(bl) << 16) | (uint32_t)__bfloat16_as_ushort(al);
}

__device__ __forceinline__ void mma16816(float* d, const uint32_t* a, const uint32_t* b) {
    asm volatile("mma.sync.aligned.m16n8k16.row.col.f32.bf16.bf16.f32 "
                 "{%0,%1,%2,%3}, {%4,%5,%6,%7}, {%8,%9}, {%0,%1,%2,%3};"
                 : "+f"(d[0]), "+f"(d[1]), "+f"(d[2]), "+f"(d[3])
                 : "r"(a[0]), "r"(a[1]), "r"(a[2]), "r"(a[3]),
                   "r"(b[0]), "r"(b[1]));
}

__device__ __forceinline__ void ldsm_x4(uint32_t* r, uint32_t a) {
    asm volatile("ldmatrix.sync.aligned.m8n8.x4.shared.b16 {%0,%1,%2,%3}, [%4];"
                 : "=r"(r[0]), "=r"(r[1]), "=r"(r[2]), "=r"(r[3]) : "r"(a) : "memory");
}

#define APITCH 72   // bf16 elems per row (144 B): 16B-aligned rows, conflict-free LDSM

// A (16x16 tile at row R, col k0): x4 ldmatrix address for lane l
__device__ __forceinline__ uint32_t a_addr(uint32_t base, int R, int l, int k0) {
    int row = R + (l & 15);
    int col = k0 + ((l >> 4) << 3);
    return base + (uint32_t)(row * APITCH + col) * 2u;
}
// B (8x16 at row n0, col k0), hi tiles in lanes 0-15, lo tiles in lanes 16-31
__device__ __forceinline__ uint32_t b_addr(uint32_t hbase, uint32_t lbase,
                                           int n0, int l, int k0) {
    uint32_t base = (l < 16) ? hbase : lbase;
    int row = n0 + (l & 7);
    int col = k0 + (((l >> 3) & 1) << 3);
    return base + (uint32_t)(row * APITCH + col) * 2u;
}

// ---------------------------------------------------------------------------
// Kernel A: node pre-transform + accumulator zeroing
// ---------------------------------------------------------------------------
__global__ void k_pre(const float* __restrict__ nf,
                      const float* __restrict__ Wsu,
                      const float* __restrict__ Wvu) {
    float* sm = (float*)dynsm;
    float* sWs  = sm;
    float* sWv  = sm + 4096;
    float* sRaw = sm + 8192;

    int tid = threadIdx.x;
    for (int i = tid; i < 4096; i += 256) { sWs[i] = Wsu[i]; sWv[i] = Wvu[i]; }

    int n0 = blockIdx.x * 32;
    for (int i = tid; i < 32 * 64; i += 256) {
        int nl = i >> 6, c4 = i & 63;
        int gn = n0 + nl;
        float4 v = make_float4(0.f, 0.f, 0.f, 0.f);
        if (gn < NN) v = ((const float4*)nf)[(size_t)gn * 64 + c4];
        ((float4*)(sRaw + nl * 256))[c4] = v;
    }
    __syncthreads();

    int kk = tid & 31;
    int g  = tid >> 5;
    int nbase = g * 4;

    float acc[4][2][4];
#pragma unroll
    for (int a = 0; a < 4; a++)
#pragma unroll
        for (int b = 0; b < 2; b++)
#pragma unroll
            for (int q = 0; q < 4; q++) acc[a][b][q] = 0.f;

    for (int c = 0; c < 64; c++) {
        float ws0 = sWs[c * 64 + kk], ws1 = sWs[c * 64 + kk + 32];
        float wv0 = sWv[c * 64 + kk], wv1 = sWv[c * 64 + kk + 32];
#pragma unroll
        for (int a = 0; a < 4; a++) {
            const float* row = sRaw + (nbase + a) * 256;
            float sv = row[c];
            float v0 = row[64 + c * 3 + 0];
            float v1 = row[64 + c * 3 + 1];
            float v2 = row[64 + c * 3 + 2];
            acc[a][0][0] += sv * ws0;  acc[a][1][0] += sv * ws1;
            acc[a][0][1] += v0 * wv0;  acc[a][1][1] += v0 * wv1;
            acc[a][0][2] += v1 * wv0;  acc[a][1][2] += v1 * wv1;
            acc[a][0][3] += v2 * wv0;  acc[a][1][3] += v2 * wv1;
        }
    }
#pragma unroll
    for (int a = 0; a < 4; a++) {
        int gn = n0 + nbase + a;
        if (gn >= NN) continue;
        ((float4*)g_pre)[(size_t)gn * 64 + kk] =
            make_float4(acc[a][0][0], acc[a][0][1], acc[a][0][2], acc[a][0][3]);
        ((float4*)g_pre)[(size_t)gn * 64 + kk + 32] =
            make_float4(acc[a][1][0], acc[a][1][1], acc[a][1][2], acc[a][1][3]);
        ((float4*)g_acc)[(size_t)gn * 64 + kk]      = make_float4(0.f, 0.f, 0.f, 0.f);
        ((float4*)g_acc)[(size_t)gn * 64 + kk + 32] = make_float4(0.f, 0.f, 0.f, 0.f);
    }
}

// ---------------------------------------------------------------------------
// Kernel B: edge kernel, mma.sync + ldmatrix. 8 warps, 16 edges/warp-group.
// ---------------------------------------------------------------------------
#define O_W1H 0u
#define O_W1L 9216u
#define O_W2H 18432u
#define O_W2L 64512u
#define O_AHI 110592u
#define O_ALO 129024u
#define O_HHI 147456u
#define O_HLO 165888u
#define O_Y   184320u
#define O_SND 185856u
#define O_RCV 186368u
#define SMEM_TC 186880u

#define NGRP (EE / 16)   // 50000

__global__ void __launch_bounds__(256, 1)
k_edge_mm(const float* __restrict__ vectors,
          const float* __restrict__ ef,
          const int* __restrict__ eidx,
          const float* __restrict__ W1,
          const float* __restrict__ W2) {
    char* sm = dynsm;
    __nv_bfloat16* W1H = (__nv_bfloat16*)(sm + O_W1H);
    __nv_bfloat16* W1L = (__nv_bfloat16*)(sm + O_W1L);
    __nv_bfloat16* W2H = (__nv_bfloat16*)(sm + O_W2H);
    __nv_bfloat16* W2L = (__nv_bfloat16*)(sm + O_W2L);
    __nv_bfloat16* AHI = (__nv_bfloat16*)(sm + O_AHI);
    __nv_bfloat16* ALO = (__nv_bfloat16*)(sm + O_ALO);
    __nv_bfloat16* HHI = (__nv_bfloat16*)(sm + O_HHI);
    __nv_bfloat16* HLO = (__nv_bfloat16*)(sm + O_HLO);
    float* sY   = (float*)(sm + O_Y);
    int*   sSnd = (int*)(sm + O_SND);
    int*   sRcv = (int*)(sm + O_RCV);

    int tid  = threadIdx.x;
    int warp = tid >> 5;
    int l    = tid & 31;

    uint32_t smb  = smem_u32(sm);
    uint32_t uW1H = smb + O_W1H, uW1L = smb + O_W1L;
    uint32_t uW2H = smb + O_W2H, uW2L = smb + O_W2L;
    uint32_t uAHI = smb + O_AHI, uALO = smb + O_ALO;
    uint32_t uHHI = smb + O_HHI, uHLO = smb + O_HLO;

    // stage W1^T, W2^T (hi/lo) once
    for (int i = tid; i < 4096; i += 256) {
        int k = i >> 6, n = i & 63;
        float v = W1[i];
        __nv_bfloat16 vh = __float2bfloat16(v);
        W1H[n * APITCH + k] = vh;
        W1L[n * APITCH + k] = __float2bfloat16(v - __bfloat162float(vh));
    }
    for (int i = tid; i < 20480; i += 256) {
        int k = i / 320, j = i - k * 320;
        float v = W2[i];
        __nv_bfloat16 vh = __float2bfloat16(v);
        W2H[j * APITCH + k] = vh;
        W2L[j * APITCH + k] = __float2bfloat16(v - __bfloat162float(vh));
    }
    __syncthreads();

    const int* snd = eidx;
    const int* rcv = eidx + EE;
    int R = warp * 16;
    int gw = blockIdx.x * 8 + warp;
    const int stride = 148 * 8;

    for (int grp = gw; grp < NGRP; grp += stride) {
        int e0 = grp * 16;

        // ---- stage 16 edges of EF, split hi/lo ----
        const float4* gsrc = (const float4*)(ef + (size_t)e0 * 64);
#pragma unroll
        for (int j = 0; j < 8; j++) {
            int idx4 = l + 32 * j;
            float4 f = gsrc[idx4];
            int idx = idx4 * 4;
            int e = idx >> 6, c = idx & 63;
            uint32_t h0, l0, h1, l1;
            split2(f.x, f.y, h0, l0);
            split2(f.z, f.w, h1, l1);
            *(uint2*)(AHI + (R + e) * APITCH + c) = make_uint2(h0, h1);
            *(uint2*)(ALO + (R + e) * APITCH + c) = make_uint2(l0, l1);
        }
        if (l < 16) {
            int ge = e0 + l;
            float vx = vectors[(size_t)ge * 3 + 0];
            float vy = vectors[(size_t)ge * 3 + 1];
            float vz = vectors[(size_t)ge * 3 + 2];
            float sc = 1.7320508075688772f /
                       (sqrtf(vx * vx + vy * vy + vz * vz) + 1e-12f);
            sY[(R + l) * 3 + 0] = vx * sc;
            sY[(R + l) * 3 + 1] = vy * sc;
            sY[(R + l) * 3 + 2] = vz * sc;
            sSnd[R + l] = snd[ge];
            sRcv[R + l] = rcv[ge];
        }
        __syncwarp();

        // ---- GEMM1: D1(16x64) = EF @ W1 (3-pass split, ldmatrix) ----
        float d1[8][4];
#pragma unroll
        for (int n = 0; n < 8; n++)
#pragma unroll
            for (int q = 0; q < 4; q++) d1[n][q] = 0.f;
#pragma unroll
        for (int ks = 0; ks < 4; ks++) {
            int k0 = ks * 16;
            uint32_t ah[4], al[4], bb[4];
            ldsm_x4(ah, a_addr(uAHI, R, l, k0));
            ldsm_x4(al, a_addr(uALO, R, l, k0));
#pragma unroll
            for (int n = 0; n < 8; n++) {
                ldsm_x4(bb, b_addr(uW1H, uW1L, n * 8, l, k0));
                mma16816(d1[n], ah, bb);      // hi*hi
                mma16816(d1[n], ah, bb + 2);  // hi*lo
                mma16816(d1[n], al, bb);      // lo*hi
            }
        }

        // ---- H = silu(D1), re-split into smem ----
        {
            int r = R + (l >> 2);
#pragma unroll
            for (int n = 0; n < 8; n++) {
                int c0 = n * 8 + (l & 3) * 2;
                uint32_t h, lo;
                split2(silu(d1[n][0]), silu(d1[n][1]), h, lo);
                *(uint32_t*)(HHI + r * APITCH + c0) = h;
                *(uint32_t*)(HLO + r * APITCH + c0) = lo;
                split2(silu(d1[n][2]), silu(d1[n][3]), h, lo);
                *(uint32_t*)(HHI + (r + 8) * APITCH + c0) = h;
                *(uint32_t*)(HLO + (r + 8) * APITCH + c0) = lo;
            }
        }
        __syncwarp();

        // ---- hoist H fragments for GEMM2 ----
        uint32_t Ah[4][4], Al[4][4];
#pragma unroll
        for (int ks = 0; ks < 4; ks++) {
            ldsm_x4(Ah[ks], a_addr(uHHI, R, l, ks * 16));
            ldsm_x4(Al[ks], a_addr(uHLO, R, l, ks * 16));
        }

        // ---- GEMM2 per 8-channel block + fused epilogue ----
#pragma unroll 1
        for (int n = 0; n < 8; n++) {
            float d2[5][4];
#pragma unroll
            for (int j = 0; j < 5; j++)
#pragma unroll
                for (int q = 0; q < 4; q++) d2[j][q] = 0.f;
#pragma unroll
            for (int ks = 0; ks < 4; ks++) {
                int k0 = ks * 16;
#pragma unroll
                for (int j = 0; j < 5; j++) {
                    uint32_t bb[4];
                    ldsm_x4(bb, b_addr(uW2H, uW2L, j * 64 + n * 8, l, k0));
                    mma16816(d2[j], Ah[ks], bb);
                    mma16816(d2[j], Ah[ks], bb + 2);
                    mma16816(d2[j], Al[ks], bb);
                }
            }
            int c0 = n * 8 + (l & 3) * 2;
#pragma unroll
            for (int half = 0; half < 2; half++) {
                int e = (l >> 2) + 8 * half;
                int sn = sSnd[R + e];
                int rc = sRcv[R + e];
                float Yx = sY[(R + e) * 3 + 0];
                float Yy = sY[(R + e) * 3 + 1];
                float Yz = sY[(R + e) * 3 + 2];
                const float4* preb = ((const float4*)g_pre) + (size_t)sn * 64;
                float4* accb = ((float4*)g_acc) + (size_t)rc * 64;
#pragma unroll
                for (int cc = 0; cc < 2; cc++) {
                    int c = c0 + cc;
                    float w0 = d2[0][2 * half + cc];
                    float w1 = d2[1][2 * half + cc];
                    float w2 = d2[2][2 * half + cc];
                    float w3 = d2[3][2 * half + cc];
                    float w4 = d2[4][2 * half + cc];
                    float4 pre = preb[c];
                    float sj = pre.x, vx = pre.y, vy = pre.z, vz = pre.w;
                    float vdY = vx * Yx + vy * Yy + vz * Yz;
                    float ms = w0 * sj + w1 * vdY;
                    float cx = vy * Yz - vz * Yy;
                    float cy = vz * Yx - vx * Yz;
                    float cz = vx * Yy - vy * Yx;
                    float t = w2 * sj;
                    float mvx = t * Yx + w3 * vx + w4 * cx;
                    float mvy = t * Yy + w3 * vy + w4 * cy;
                    float mvz = t * Yz + w3 * vz + w4 * cz;
                    float4* dst = accb + c;
                    asm volatile("red.global.add.v4.f32 [%0], {%1,%2,%3,%4};"
                                 :: "l"(dst), "f"(ms), "f"(mvx), "f"(mvy), "f"(mvz)
                                 : "memory");
                }
            }
        }
        __syncwarp();
    }
}

// ---------------------------------------------------------------------------
// Kernel C: node post (persistent), transposed weights + float4 loads
// ---------------------------------------------------------------------------
#define NB   8
#define TB_C 512
#define NT_C (NN / NB)
#define PT   68     // transposed weight pitch (floats): conflict-free LDS.128
#define F_RG   47872
#define F_RVM  47936
#define F_RSV  48000
#define F_ASV  50048
#define F_VV   52096
#define F_PSB  52608
#define F_PVM  53120
#define F_HR   55168
#define F_VS   55680
#define SMEM_C_BYTES (55712 * 4)

__global__ void __launch_bounds__(TB_C, 1)
k_post(const float* __restrict__ Wsp, const float* __restrict__ Wvp,
       const float* __restrict__ Ps1w, const float* __restrict__ Ps2w,
       const float* __restrict__ Ps3w, const float* __restrict__ Pvvw,
       const float* __restrict__ Pv1w, const float* __restrict__ Pv2w,
       const float* __restrict__ Pv3w, const float* __restrict__ Rw1,
       const float* __restrict__ Rw2, const float* __restrict__ Rg,
       const float* __restrict__ Rvm, float* __restrict__ out) {
    float* sm = (float*)dynsm;
    float* T0  = sm + 0 * 4352;   // WspT
    float* T1  = sm + 1 * 4352;   // WvpT
    float* T2  = sm + 2 * 4352;   // Ps1T
    float* T3  = sm + 3 * 4352;   // Ps2T
    float* T4  = sm + 4 * 4352;   // Ps3T
    float* T5  = sm + 5 * 4352;   // PvvT
    float* T6  = sm + 6 * 4352;   // Pv1T
    float* T7  = sm + 7 * 4352;   // Pv2T
    float* T8  = sm + 8 * 4352;   // Pv3T
    float* T9  = sm + 9 * 4352;   // Rw1T
    float* T10 = sm + 10 * 4352;  // Rw2T
    float* sRg  = sm + F_RG;
    float* sRvm = sm + F_RVM;
    float4* sRsv = (float4*)(sm + F_RSV);
    float4* sAsv = (float4*)(sm + F_ASV);
    float*  sVv  = sm + F_VV;
    float*  sPsb = sm + F_PSB;
    float4* sPvm = (float4*)(sm + F_PVM);
    float*  sHr  = sm + F_HR;
    float*  sVs  = sm + F_VS;

    int tid = threadIdx.x;
    // transposed weight staging: write conflict-free, read gmem strided (one-time)
    for (int i = tid; i < 4096; i += TB_C) {
        int c = i & 63, kq = i >> 6;
        int dst = kq * PT + c;
        int src = c * 64 + kq;
        T0[dst] = Wsp[src];  T1[dst] = Wvp[src];
        T2[dst] = Ps1w[src]; T3[dst] = Ps2w[src]; T4[dst] = Ps3w[src];
        T5[dst] = Pvvw[src];
        T6[dst] = Pv1w[src]; T7[dst] = Pv2w[src]; T8[dst] = Pv3w[src];
        T9[dst] = Rw1[src];  T10[dst] = Rw2[src];
    }
    if (tid < 64) { sRg[tid] = Rg[tid]; sRvm[tid] = Rvm[tid]; }

    int k = tid & 63;
    int g = tid >> 6;
    float* out_s  = out;
    float* out_v  = out + (size_t)NN * 64;
    float* out_nf = out + (size_t)NN * 67;

    for (int tile = blockIdx.x; tile < NT_C; tile += gridDim.x) {
        int gn = tile * NB + g;
        __syncthreads();

        // stage 1: load accumulated messages, scale
        {
            float4 r4 = ((const float4*)g_acc)[(size_t)gn * 64 + k];
            const float inv = 1.0f / 16.0f;
            sRsv[g * 64 + k] = make_float4(r4.x * inv, r4.y * inv, r4.z * inv, r4.w * inv);
        }
        __syncthreads();

        // stage 2: a_s@Wsp, a_v@Wvp, vv
        {
            float as = 0.f, av0 = 0.f, av1 = 0.f, av2 = 0.f;
            const float4* wsT = (const float4*)(T0 + k * PT);
            const float4* wvT = (const float4*)(T1 + k * PT);
            const float4* rv  = sRsv + g * 64;
#pragma unroll 4
            for (int c4 = 0; c4 < 16; c4++) {
                float4 ws = wsT[c4], wv = wvT[c4];
                float4 x0 = rv[c4 * 4 + 0], x1 = rv[c4 * 4 + 1];
                float4 x2 = rv[c4 * 4 + 2], x3 = rv[c4 * 4 + 3];
                as  += x0.x * ws.x + x1.x * ws.y + x2.x * ws.z + x3.x * ws.w;
                av0 += x0.y * wv.x + x1.y * wv.y + x2.y * wv.z + x3.y * wv.w;
                av1 += x0.z * wv.x + x1.z * wv.y + x2.z * wv.z + x3.z * wv.w;
                av2 += x0.w * wv.x + x1.w * wv.y + x2.w * wv.z + x3.w * wv.w;
            }
            sAsv[g * 64 + k] = make_float4(as, av0, av1, av2);
            sVv[g * 64 + k] = av0 * av0 + av1 * av1 + av2 * av2;
        }
        __syncthreads();

        // stage 3: ps / pv polynomial mix
        {
            float ps = 0.f, pv0 = 0.f, pv1 = 0.f, pv2 = 0.f;
            const float4* P1 = (const float4*)(T2 + k * PT);
            const float4* P2 = (const float4*)(T3 + k * PT);
            const float4* P3 = (const float4*)(T4 + k * PT);
            const float4* PW = (const float4*)(T5 + k * PT);
            const float4* Q1 = (const float4*)(T6 + k * PT);
            const float4* Q2 = (const float4*)(T7 + k * PT);
            const float4* Q3 = (const float4*)(T8 + k * PT);
            const float4* AV = sAsv + g * 64;
            const float4* VV = (const float4*)(sVv + g * 64);
#pragma unroll 2
            for (int c4 = 0; c4 < 16; c4++) {
                float4 p1 = P1[c4], p2 = P2[c4], p3 = P3[c4], pw = PW[c4];
                float4 q1 = Q1[c4], q2 = Q2[c4], q3 = Q3[c4];
                float4 vv = VV[c4];
                float4 a0 = AV[c4 * 4 + 0], a1 = AV[c4 * 4 + 1];
                float4 a2v = AV[c4 * 4 + 2], a3v = AV[c4 * 4 + 3];
#define S3(avv, CM) do { \
                float a = (avv).x; float a2 = a * a; float a3 = a2 * a; \
                ps += a * p1.CM + a2 * p2.CM + a3 * p3.CM + vv.CM * pw.CM; \
                float q = q1.CM + a * q2.CM + a2 * q3.CM; \
                pv0 += (avv).y * q; pv1 += (avv).z * q; pv2 += (avv).w * q; } while (0)
                S3(a0, x); S3(a1, y); S3(a2v, z); S3(a3v, w);
#undef S3
            }
            sPsb[g * 64 + k] = ps;
            float rv = sRvm[k];
            sPvm[g * 64 + k] = make_float4(pv0 * rv, pv1 * rv, pv2 * rv, 0.f);
            out_nf[(size_t)gn * 256 + k] = ps;
            out_nf[(size_t)gn * 256 + 64 + k * 3 + 0] = pv0;
            out_nf[(size_t)gn * 256 + 64 + k * 3 + 1] = pv1;
            out_nf[(size_t)gn * 256 + 64 + k * 3 + 2] = pv2;
        }
        __syncthreads();

        // stage 4: hr = silu(ps @ R_w1); vec partial reduce
        {
            float hr = 0.f;
            const float4* W1T = (const float4*)(T9 + k * PT);
            const float4* PS = (const float4*)(sPsb + g * 64);
#pragma unroll 4
            for (int c4 = 0; c4 < 16; c4++) {
                float4 w = W1T[c4], p = PS[c4];
                hr += p.x * w.x + p.y * w.y + p.z * w.z + p.w * w.w;
            }
            hr = silu(hr);
            sHr[g * 64 + k] = hr;
            if (k < 3) {
                const float* pvf = (const float*)(sPvm + g * 64);
                float s = 0.f;
                for (int c = 0; c < 64; c++) s += pvf[c * 4 + k];
                sVs[g * 4 + k] = s;
            }
        }
        __syncthreads();

        // stage 5: out_s, gate, vec
        {
            float os = 0.f, gs = 0.f;
            const float4* W2T = (const float4*)(T10 + k * PT);
            const float4* H4 = (const float4*)(sHr + g * 64);
            const float4* G4 = (const float4*)sRg;
#pragma unroll 4
            for (int m4 = 0; m4 < 16; m4++) {
                float4 w = W2T[m4], h = H4[m4], gg = G4[m4];
                os += h.x * w.x + h.y * w.y + h.z * w.z + h.w * w.w;
                gs += h.x * gg.x + h.y * gg.y + h.z * gg.z + h.w * gg.w;
            }
            out_s[(size_t)gn * 64 + k] = os;
            float gate = silu(gs);
            if (k < 3) out_v[(size_t)gn * 3 + k] = sVs[g * 4 + k] * gate;
        }
    }
}

// ---------------------------------------------------------------------------
extern "C" void kernel_launch(void* const* d_in, const int* in_sizes, int n_in,
                              void* d_out, int out_size) {
    const float* vectors    = (const float*)d_in[0];
    const float* node_feats = (const float*)d_in[2];
    const float* edge_feats = (const float*)d_in[3];
    const int*   eidx       = (const int*)d_in[4];
    const float* Wsu        = (const float*)d_in[5];
    const float* Wvu        = (const float*)d_in[6];
    const float* W1         = (const float*)d_in[7];
    const float* W2         = (const float*)d_in[8];
    const float* Wsp        = (const float*)d_in[9];
    const float* Wvp        = (const float*)d_in[10];
    const float* Ps1        = (const float*)d_in[11];
    const float* Ps2        = (const float*)d_in[12];
    const float* Ps3        = (const float*)d_in[13];
    const float* Pvv        = (const float*)d_in[14];
    const float* Pv1        = (const float*)d_in[15];
    const float* Pv2        = (const float*)d_in[16];
    const float* Pv3        = (const float*)d_in[17];
    const float* Rw1        = (const float*)d_in[18];
    const float* Rw2        = (const float*)d_in[19];
    const float* Rg         = (const float*)d_in[20];
    const float* Rvm        = (const float*)d_in[21];
    float* out = (float*)d_out;

    const int SMEM_A_BYTES = (4096 + 4096 + 32 * 256) * 4;
    cudaFuncSetAttribute(k_pre,     cudaFuncAttributeMaxDynamicSharedMemorySize, SMEM_A_BYTES);
    cudaFuncSetAttribute(k_edge_mm, cudaFuncAttributeMaxDynamicSharedMemorySize, SMEM_TC);
    cudaFuncSetAttribute(k_post,    cudaFuncAttributeMaxDynamicSharedMemorySize, SMEM_C_BYTES);

    k_pre<<<(NN + 31) / 32, 256, SMEM_A_BYTES>>>(node_feats, Wsu, Wvu);
    k_edge_mm<<<148, 256, SMEM_TC>>>(vectors, edge_feats, eidx, W1, W2);
    k_post<<<148, TB_C, SMEM_C_BYTES>>>(Wsp, Wvp, Ps1, Ps2, Ps3, Pvv,
                                        Pv1, Pv2, Pv3, Rw1, Rw2, Rg, Rvm, out);
}

// round 14
// speedup vs baseline: 1.1850x; 1.1850x over previous
#include <cuda_runtime.h>
#include <cuda_bf16.h>
#include <math.h>
#include <stdint.h>

#define NN 50000
#define EE 800000

extern __shared__ char dynsm[];

__device__ float g_pre[(size_t)NN * 64 * 4];
__device__ float g_acc[(size_t)NN * 64 * 4];

__device__ __forceinline__ float silu(float x) {
    return x * (1.0f / (1.0f + __expf(-x)));
}

// split a pair of floats into bf16 hi and lo packed u32s
__device__ __forceinline__ void split2(float a, float b, uint32_t& hi, uint32_t& lo) {
    __nv_bfloat16 ah = __float2bfloat16(a);
    __nv_bfloat16 bh = __float2bfloat16(b);
    __nv_bfloat16 al = __float2bfloat16(a - __bfloat162float(ah));
    __nv_bfloat16 bl = __float2bfloat16(b - __bfloat162float(bh));
    hi = ((uint32_t)__bfloat16_as_ushort(bh) << 16) | (uint32_t)__bfloat16_as_ushort(ah);
    lo = ((uint32_t)__bfloat16_as_ushort(bl) << 16) | (uint32_t)__bfloat16_as_ushort(al);
}

// m16n8k16 row.col bf16 -> f32 accum (baseline PTX, works on plain sm_103)
__device__ __forceinline__ void mma16816(float* d, const uint32_t* a, const uint32_t* b) {
    asm volatile("mma.sync.aligned.m16n8k16.row.col.f32.bf16.bf16.f32 "
                 "{%0,%1,%2,%3}, {%4,%5,%6,%7}, {%8,%9}, {%0,%1,%2,%3};"
                 : "+f"(d[0]), "+f"(d[1]), "+f"(d[2]), "+f"(d[3])
                 : "r"(a[0]), "r"(a[1]), "r"(a[2]), "r"(a[3]),
                   "r"(b[0]), "r"(b[1]));
}

#define APITCH 72   // bf16 elems per row (144 B) -> conflict-light fragment access

// A fragment: rows R+(l>>2), R+(l>>2)+8 ; k-cols k0+(l&3)*2 (+8)
__device__ __forceinline__ void lda_frag(uint32_t* a, const __nv_bfloat16* base,
                                         int R, int l, int k0) {
    int r = R + (l >> 2);
    int c = k0 + (l & 3) * 2;
    a[0] = *(const uint32_t*)(base + r * APITCH + c);
    a[1] = *(const uint32_t*)(base + (r + 8) * APITCH + c);
    a[2] = *(const uint32_t*)(base + r * APITCH + c + 8);
    a[3] = *(const uint32_t*)(base + (r + 8) * APITCH + c + 8);
}
// B fragment (col-major k x n): Wt stored [n][k]
__device__ __forceinline__ void ldb_frag(uint32_t* b, const __nv_bfloat16* base,
                                         int n0, int l, int k0) {
    int n = n0 + (l >> 2);
    int k = k0 + (l & 3) * 2;
    b[0] = *(const uint32_t*)(base + n * APITCH + k);
    b[1] = *(const uint32_t*)(base + n * APITCH + k + 8);
}

// ---------------------------------------------------------------------------
// Kernel A: node pre-transform + accumulator zeroing
// ---------------------------------------------------------------------------
__global__ void k_pre(const float* __restrict__ nf,
                      const float* __restrict__ Wsu,
                      const float* __restrict__ Wvu) {
    float* sm = (float*)dynsm;
    float* sWs  = sm;
    float* sWv  = sm + 4096;
    float* sRaw = sm + 8192;

    int tid = threadIdx.x;
    for (int i = tid; i < 4096; i += 256) { sWs[i] = Wsu[i]; sWv[i] = Wvu[i]; }

    int n0 = blockIdx.x * 32;
    for (int i = tid; i < 32 * 64; i += 256) {
        int nl = i >> 6, c4 = i & 63;
        int gn = n0 + nl;
        float4 v = make_float4(0.f, 0.f, 0.f, 0.f);
        if (gn < NN) v = ((const float4*)nf)[(size_t)gn * 64 + c4];
        ((float4*)(sRaw + nl * 256))[c4] = v;
    }
    __syncthreads();

    int kk = tid & 31;
    int g  = tid >> 5;
    int nbase = g * 4;

    float acc[4][2][4];
#pragma unroll
    for (int a = 0; a < 4; a++)
#pragma unroll
        for (int b = 0; b < 2; b++)
#pragma unroll
            for (int q = 0; q < 4; q++) acc[a][b][q] = 0.f;

    for (int c = 0; c < 64; c++) {
        float ws0 = sWs[c * 64 + kk], ws1 = sWs[c * 64 + kk + 32];
        float wv0 = sWv[c * 64 + kk], wv1 = sWv[c * 64 + kk + 32];
#pragma unroll
        for (int a = 0; a < 4; a++) {
            const float* row = sRaw + (nbase + a) * 256;
            float sv = row[c];
            float v0 = row[64 + c * 3 + 0];
            float v1 = row[64 + c * 3 + 1];
            float v2 = row[64 + c * 3 + 2];
            acc[a][0][0] += sv * ws0;  acc[a][1][0] += sv * ws1;
            acc[a][0][1] += v0 * wv0;  acc[a][1][1] += v0 * wv1;
            acc[a][0][2] += v1 * wv0;  acc[a][1][2] += v1 * wv1;
            acc[a][0][3] += v2 * wv0;  acc[a][1][3] += v2 * wv1;
        }
    }
#pragma unroll
    for (int a = 0; a < 4; a++) {
        int gn = n0 + nbase + a;
        if (gn >= NN) continue;
        ((float4*)g_pre)[(size_t)gn * 64 + kk] =
            make_float4(acc[a][0][0], acc[a][0][1], acc[a][0][2], acc[a][0][3]);
        ((float4*)g_pre)[(size_t)gn * 64 + kk + 32] =
            make_float4(acc[a][1][0], acc[a][1][1], acc[a][1][2], acc[a][1][3]);
        ((float4*)g_acc)[(size_t)gn * 64 + kk]      = make_float4(0.f, 0.f, 0.f, 0.f);
        ((float4*)g_acc)[(size_t)gn * 64 + kk + 32] = make_float4(0.f, 0.f, 0.f, 0.f);
    }
}

// ---------------------------------------------------------------------------
// Kernel B: edge kernel via mma.sync (HMMA). 8 warps; 16 edges per warp-tile.
// R7 base + hoisted H fragments + double-buffered g_pre gather.
// ---------------------------------------------------------------------------
#define O_W1H 0u
#define O_W1L 9216u
#define O_W2H 18432u
#define O_W2L 64512u
#define O_AHI 110592u
#define O_ALO 129024u
#define O_HHI 147456u
#define O_HLO 165888u
#define O_Y   184320u
#define O_SND 185856u
#define O_RCV 186368u
#define SMEM_TC 186880u

#define NGRP (EE / 16)   // 50000

__global__ void __launch_bounds__(256, 1)
k_edge_mm(const float* __restrict__ vectors,
          const float* __restrict__ ef,
          const int* __restrict__ eidx,
          const float* __restrict__ W1,
          const float* __restrict__ W2) {
    char* sm = dynsm;
    __nv_bfloat16* W1H = (__nv_bfloat16*)(sm + O_W1H);
    __nv_bfloat16* W1L = (__nv_bfloat16*)(sm + O_W1L);
    __nv_bfloat16* W2H = (__nv_bfloat16*)(sm + O_W2H);
    __nv_bfloat16* W2L = (__nv_bfloat16*)(sm + O_W2L);
    __nv_bfloat16* AHI = (__nv_bfloat16*)(sm + O_AHI);
    __nv_bfloat16* ALO = (__nv_bfloat16*)(sm + O_ALO);
    __nv_bfloat16* HHI = (__nv_bfloat16*)(sm + O_HHI);
    __nv_bfloat16* HLO = (__nv_bfloat16*)(sm + O_HLO);
    float* sY   = (float*)(sm + O_Y);
    int*   sSnd = (int*)(sm + O_SND);
    int*   sRcv = (int*)(sm + O_RCV);

    int tid  = threadIdx.x;
    int warp = tid >> 5;
    int l    = tid & 31;

    // stage W1^T, W2^T (hi/lo) once
    for (int i = tid; i < 4096; i += 256) {
        int k = i >> 6, n = i & 63;
        float v = W1[i];
        __nv_bfloat16 vh = __float2bfloat16(v);
        W1H[n * APITCH + k] = vh;
        W1L[n * APITCH + k] = __float2bfloat16(v - __bfloat162float(vh));
    }
    for (int i = tid; i < 20480; i += 256) {
        int k = i / 320, j = i - k * 320;
        float v = W2[i];
        __nv_bfloat16 vh = __float2bfloat16(v);
        W2H[j * APITCH + k] = vh;
        W2L[j * APITCH + k] = __float2bfloat16(v - __bfloat162float(vh));
    }
    __syncthreads();

    const int* snd = eidx;
    const int* rcv = eidx + EE;
    int R = warp * 16;
    int gw = blockIdx.x * 8 + warp;
    const int stride = 148 * 8;

    for (int grp = gw; grp < NGRP; grp += stride) {
        int e0 = grp * 16;

        // ---- stage 16 edges of EF, split hi/lo ----
        const float4* gsrc = (const float4*)(ef + (size_t)e0 * 64);
#pragma unroll
        for (int j = 0; j < 8; j++) {
            int idx4 = l + 32 * j;
            float4 f = gsrc[idx4];
            int idx = idx4 * 4;
            int e = idx >> 6, c = idx & 63;
            uint32_t h0, l0, h1, l1;
            split2(f.x, f.y, h0, l0);
            split2(f.z, f.w, h1, l1);
            *(uint2*)(AHI + (R + e) * APITCH + c) = make_uint2(h0, h1);
            *(uint2*)(ALO + (R + e) * APITCH + c) = make_uint2(l0, l1);
        }
        if (l < 16) {
            int ge = e0 + l;
            float vx = vectors[(size_t)ge * 3 + 0];
            float vy = vectors[(size_t)ge * 3 + 1];
            float vz = vectors[(size_t)ge * 3 + 2];
            float sc = 1.7320508075688772f /
                       (sqrtf(vx * vx + vy * vy + vz * vz) + 1e-12f);
            sY[(R + l) * 3 + 0] = vx * sc;
            sY[(R + l) * 3 + 1] = vy * sc;
            sY[(R + l) * 3 + 2] = vz * sc;
            sSnd[R + l] = snd[ge];
            sRcv[R + l] = rcv[ge];
        }
        __syncwarp();

        // ---- GEMM1: D1(16x64) = EF @ W1 (3-pass split) ----
        float d1[8][4];
#pragma unroll
        for (int n = 0; n < 8; n++)
#pragma unroll
            for (int q = 0; q < 4; q++) d1[n][q] = 0.f;
#pragma unroll
        for (int ks = 0; ks < 4; ks++) {
            int k0 = ks * 16;
            uint32_t ah[4], al[4];
            lda_frag(ah, AHI, R, l, k0);
            lda_frag(al, ALO, R, l, k0);
#pragma unroll
            for (int n = 0; n < 8; n++) {
                uint32_t bh[2], bl[2];
                ldb_frag(bh, W1H, n * 8, l, k0);
                ldb_frag(bl, W1L, n * 8, l, k0);
                mma16816(d1[n], ah, bh);
                mma16816(d1[n], ah, bl);
                mma16816(d1[n], al, bh);
            }
        }

        // ---- H = silu(D1), re-split into smem ----
        {
            int r = R + (l >> 2);
#pragma unroll
            for (int n = 0; n < 8; n++) {
                int c0 = n * 8 + (l & 3) * 2;
                uint32_t h, lo;
                split2(silu(d1[n][0]), silu(d1[n][1]), h, lo);
                *(uint32_t*)(HHI + r * APITCH + c0) = h;
                *(uint32_t*)(HLO + r * APITCH + c0) = lo;
                split2(silu(d1[n][2]), silu(d1[n][3]), h, lo);
                *(uint32_t*)(HHI + (r + 8) * APITCH + c0) = h;
                *(uint32_t*)(HLO + (r + 8) * APITCH + c0) = lo;
            }
        }
        __syncwarp();

        // ---- hoist epilogue invariants (per-thread edge rows) ----
        int eA = l >> 2, eB = eA + 8;
        int cc0 = (l & 3) * 2;
        int snA = sSnd[R + eA], rcA = sRcv[R + eA];
        int snB = sSnd[R + eB], rcB = sRcv[R + eB];
        float YxA = sY[(R + eA) * 3 + 0];
        float YyA = sY[(R + eA) * 3 + 1];
        float YzA = sY[(R + eA) * 3 + 2];
        float YxB = sY[(R + eB) * 3 + 0];
        float YyB = sY[(R + eB) * 3 + 1];
        float YzB = sY[(R + eB) * 3 + 2];
        const float4* prebA = ((const float4*)g_pre) + (size_t)snA * 64;
        const float4* prebB = ((const float4*)g_pre) + (size_t)snB * 64;
        float4* accbA = ((float4*)g_acc) + (size_t)rcA * 64;
        float4* accbB = ((float4*)g_acc) + (size_t)rcB * 64;

        // prime gather for n=0 (overlaps with fragment hoist below)
        float4 pA0 = prebA[cc0], pA1 = prebA[cc0 + 1];
        float4 pB0 = prebB[cc0], pB1 = prebB[cc0 + 1];

        // ---- hoist H fragments across the n loop ----
        uint32_t Ah[4][4], Al[4][4];
#pragma unroll
        for (int ks = 0; ks < 4; ks++) {
            lda_frag(Ah[ks], HHI, R, l, ks * 16);
            lda_frag(Al[ks], HLO, R, l, ks * 16);
        }

        // ---- GEMM2 per 8-channel block + pipelined epilogue ----
#pragma unroll 1
        for (int n = 0; n < 8; n++) {
            float d2[5][4];
#pragma unroll
            for (int j = 0; j < 5; j++)
#pragma unroll
                for (int q = 0; q < 4; q++) d2[j][q] = 0.f;
#pragma unroll
            for (int ks = 0; ks < 4; ks++) {
                int k0 = ks * 16;
#pragma unroll
                for (int j = 0; j < 5; j++) {
                    uint32_t bh[2], bl[2];
                    ldb_frag(bh, W2H, j * 64 + n * 8, l, k0);
                    ldb_frag(bl, W2L, j * 64 + n * 8, l, k0);
                    mma16816(d2[j], Ah[ks], bh);
                    mma16816(d2[j], Ah[ks], bl);
                    mma16816(d2[j], Al[ks], bh);
                }
            }

            // prefetch gather for n+1 (consumed after next block's MMA chain)
            float4 nA0, nA1, nB0, nB1;
            if (n < 7) {
                int cn = (n + 1) * 8 + cc0;
                nA0 = prebA[cn]; nA1 = prebA[cn + 1];
                nB0 = prebB[cn]; nB1 = prebB[cn + 1];
            }

            int c0 = n * 8 + cc0;
            // half 0: edge row eA, channels c0 / c0+1
            {
                float4 pr[2] = {pA0, pA1};
#pragma unroll
                for (int cc = 0; cc < 2; cc++) {
                    float w0 = d2[0][cc], w1 = d2[1][cc], w2 = d2[2][cc];
                    float w3 = d2[3][cc], w4 = d2[4][cc];
                    float sj = pr[cc].x, vx = pr[cc].y, vy = pr[cc].z, vz = pr[cc].w;
                    float vdY = vx * YxA + vy * YyA + vz * YzA;
                    float ms = w0 * sj + w1 * vdY;
                    float cx = vy * YzA - vz * YyA;
                    float cy = vz * YxA - vx * YzA;
                    float cz = vx * YyA - vy * YxA;
                    float t = w2 * sj;
                    float mvx = t * YxA + w3 * vx + w4 * cx;
                    float mvy = t * YyA + w3 * vy + w4 * cy;
                    float mvz = t * YzA + w3 * vz + w4 * cz;
                    float4* dst = accbA + (c0 + cc);
                    asm volatile("red.global.add.v4.f32 [%0], {%1,%2,%3,%4};"
                                 :: "l"(dst), "f"(ms), "f"(mvx), "f"(mvy), "f"(mvz)
                                 : "memory");
                }
            }
            // half 1: edge row eB, channels c0 / c0+1
            {
                float4 pr[2] = {pB0, pB1};
#pragma unroll
                for (int cc = 0; cc < 2; cc++) {
                    float w0 = d2[0][2 + cc], w1 = d2[1][2 + cc], w2 = d2[2][2 + cc];
                    float w3 = d2[3][2 + cc], w4 = d2[4][2 + cc];
                    float sj = pr[cc].x, vx = pr[cc].y, vy = pr[cc].z, vz = pr[cc].w;
                    float vdY = vx * YxB + vy * YyB + vz * YzB;
                    float ms = w0 * sj + w1 * vdY;
                    float cx = vy * YzB - vz * YyB;
                    float cy = vz * YxB - vx * YzB;
                    float cz = vx * YyB - vy * YxB;
                    float t = w2 * sj;
                    float mvx = t * YxB + w3 * vx + w4 * cx;
                    float mvy = t * YyB + w3 * vy + w4 * cy;
                    float mvz = t * YzB + w3 * vz + w4 * cz;
                    float4* dst = accbB + (c0 + cc);
                    asm volatile("red.global.add.v4.f32 [%0], {%1,%2,%3,%4};"
                                 :: "l"(dst), "f"(ms), "f"(mvx), "f"(mvy), "f"(mvz)
                                 : "memory");
                }
            }
            pA0 = nA0; pA1 = nA1; pB0 = nB0; pB1 = nB1;
        }
        __syncwarp();
    }
}

// ---------------------------------------------------------------------------
// Kernel C: node post (persistent) — exact R7 version (known-good perf)
// ---------------------------------------------------------------------------
#define NB   8
#define TB_C 512
#define NT_C (NN / NB)
#define SMEM_C_BYTES ((11 * 4096 + 64 + 64 + 512 + 1536 + 512 + 512 + 1536 + 512 + 512 + 32) * 4)

__global__ void k_post(const float* __restrict__ Wsp, const float* __restrict__ Wvp,
                       const float* __restrict__ Ps1w, const float* __restrict__ Ps2w,
                       const float* __restrict__ Ps3w, const float* __restrict__ Pvvw,
                       const float* __restrict__ Pv1w, const float* __restrict__ Pv2w,
                       const float* __restrict__ Pv3w, const float* __restrict__ Rw1,
                       const float* __restrict__ Rw2, const float* __restrict__ Rg,
                       const float* __restrict__ Rvm, float* __restrict__ out) {
    float* sm = (float*)dynsm;
    float* sWsp = sm + 0 * 4096;
    float* sWvp = sm + 1 * 4096;
    float* sPs1 = sm + 2 * 4096;
    float* sPs2 = sm + 3 * 4096;
    float* sPs3 = sm + 4 * 4096;
    float* sPvv = sm + 5 * 4096;
    float* sPv1 = sm + 6 * 4096;
    float* sPv2 = sm + 7 * 4096;
    float* sPv3 = sm + 8 * 4096;
    float* sRw1 = sm + 9 * 4096;
    float* sRw2 = sm + 10 * 4096;
    float* sRg  = sm + 11 * 4096;
    float* sRvm = sRg + 64;
    float* sRs  = sRvm + 64;
    float* sRv  = sRs + 512;
    float* sAs  = sRv + 1536;
    float* sVv  = sAs + 512;
    float* sAv  = sVv + 512;
    float* sPsb = sAv + 1536;
    float* sHr  = sPsb + 512;
    float* sVs  = sHr + 512;

    int tid = threadIdx.x;
    for (int i = tid; i < 4096; i += TB_C) {
        sWsp[i] = Wsp[i];  sWvp[i] = Wvp[i];
        sPs1[i] = Ps1w[i]; sPs2[i] = Ps2w[i]; sPs3[i] = Ps3w[i];
        sPvv[i] = Pvvw[i];
        sPv1[i] = Pv1w[i]; sPv2[i] = Pv2w[i]; sPv3[i] = Pv3w[i];
        sRw1[i] = Rw1[i];  sRw2[i] = Rw2[i];
    }
    if (tid < 64) { sRg[tid] = Rg[tid]; sRvm[tid] = Rvm[tid]; }

    int k = tid & 63;
    int g = tid >> 6;
    float* out_s  = out;
    float* out_v  = out + (size_t)NN * 64;
    float* out_nf = out + (size_t)NN * 67;

    for (int tile = blockIdx.x; tile < NT_C; tile += gridDim.x) {
        int gn = tile * NB + g;
        __syncthreads();

        float4 r4 = ((const float4*)g_acc)[(size_t)gn * 64 + k];
        const float inv = 1.0f / 16.0f;
        sRs[g * 64 + k] = r4.x * inv;
        sRv[(g * 64 + k) * 3 + 0] = r4.y * inv;
        sRv[(g * 64 + k) * 3 + 1] = r4.z * inv;
        sRv[(g * 64 + k) * 3 + 2] = r4.w * inv;
        __syncthreads();

        float as = 0.f, av0 = 0.f, av1 = 0.f, av2 = 0.f;
        for (int c = 0; c < 64; c++) {
            float wsp = sWsp[c * 64 + k];
            float wvp = sWvp[c * 64 + k];
            float rs = sRs[g * 64 + c];
            float r0 = sRv[(g * 64 + c) * 3 + 0];
            float r1 = sRv[(g * 64 + c) * 3 + 1];
            float r2 = sRv[(g * 64 + c) * 3 + 2];
            as += rs * wsp; av0 += r0 * wvp; av1 += r1 * wvp; av2 += r2 * wvp;
        }
        sAs[g * 64 + k] = as;
        sAv[(g * 64 + k) * 3 + 0] = av0;
        sAv[(g * 64 + k) * 3 + 1] = av1;
        sAv[(g * 64 + k) * 3 + 2] = av2;
        sVv[g * 64 + k] = av0 * av0 + av1 * av1 + av2 * av2;
        __syncthreads();

        float ps = 0.f, pv0 = 0.f, pv1 = 0.f, pv2 = 0.f;
        for (int c = 0; c < 64; c++) {
            float a = sAs[g * 64 + c];
            float a2 = a * a;
            float a3 = a2 * a;
            float vvc = sVv[g * 64 + c];
            ps += a * sPs1[c * 64 + k] + a2 * sPs2[c * 64 + k]
                + a3 * sPs3[c * 64 + k] + vvc * sPvv[c * 64 + k];
            float q = sPv1[c * 64 + k] + a * sPv2[c * 64 + k] + a2 * sPv3[c * 64 + k];
            pv0 += sAv[(g * 64 + c) * 3 + 0] * q;
            pv1 += sAv[(g * 64 + c) * 3 + 1] * q;
            pv2 += sAv[(g * 64 + c) * 3 + 2] * q;
        }
        sPsb[g * 64 + k] = ps;
        float rv = sRvm[k];
        sRv[(g * 64 + k) * 3 + 0] = pv0 * rv;
        sRv[(g * 64 + k) * 3 + 1] = pv1 * rv;
        sRv[(g * 64 + k) * 3 + 2] = pv2 * rv;
        out_nf[(size_t)gn * 256 + k] = ps;
        out_nf[(size_t)gn * 256 + 64 + k * 3 + 0] = pv0;
        out_nf[(size_t)gn * 256 + 64 + k * 3 + 1] = pv1;
        out_nf[(size_t)gn * 256 + 64 + k * 3 + 2] = pv2;
        __syncthreads();

        float hr = 0.f;
        for (int c = 0; c < 64; c++) hr += sPsb[g * 64 + c] * sRw1[c * 64 + k];
        hr = silu(hr);
        sHr[g * 64 + k] = hr;
        if (k < 3) {
            float s = 0.f;
            for (int c = 0; c < 64; c++) s += sRv[(g * 64 + c) * 3 + k];
            sVs[g * 4 + k] = s;
        }
        __syncthreads();

        float os = 0.f, gs = 0.f;
        for (int m = 0; m < 64; m++) {
            float h = sHr[g * 64 + m];
            os += h * sRw2[m * 64 + k];
            gs += h * sRg[m];
        }
        out_s[(size_t)gn * 64 + k] = os;
        float gate = silu(gs);
        if (k < 3) out_v[(size_t)gn * 3 + k] = sVs[g * 4 + k] * gate;
    }
}

// ---------------------------------------------------------------------------
extern "C" void kernel_launch(void* const* d_in, const int* in_sizes, int n_in,
                              void* d_out, int out_size) {
    const float* vectors    = (const float*)d_in[0];
    const float* node_feats = (const float*)d_in[2];
    const float* edge_feats = (const float*)d_in[3];
    const int*   eidx       = (const int*)d_in[4];
    const float* Wsu        = (const float*)d_in[5];
    const float* Wvu        = (const float*)d_in[6];
    const float* W1         = (const float*)d_in[7];
    const float* W2         = (const float*)d_in[8];
    const float* Wsp        = (const float*)d_in[9];
    const float* Wvp        = (const float*)d_in[10];
    const float* Ps1        = (const float*)d_in[11];
    const float* Ps2        = (const float*)d_in[12];
    const float* Ps3        = (const float*)d_in[13];
    const float* Pvv        = (const float*)d_in[14];
    const float* Pv1        = (const float*)d_in[15];
    const float* Pv2        = (const float*)d_in[16];
    const float* Pv3        = (const float*)d_in[17];
    const float* Rw1        = (const float*)d_in[18];
    const float* Rw2        = (const float*)d_in[19];
    const float* Rg         = (const float*)d_in[20];
    const float* Rvm        = (const float*)d_in[21];
    float* out = (float*)d_out;

    const int SMEM_A_BYTES = (4096 + 4096 + 32 * 256) * 4;
    cudaFuncSetAttribute(k_pre,     cudaFuncAttributeMaxDynamicSharedMemorySize, SMEM_A_BYTES);
    cudaFuncSetAttribute(k_edge_mm, cudaFuncAttributeMaxDynamicSharedMemorySize, SMEM_TC);
    cudaFuncSetAttribute(k_post,    cudaFuncAttributeMaxDynamicSharedMemorySize, SMEM_C_BYTES);

    k_pre<<<(NN + 31) / 32, 256, SMEM_A_BYTES>>>(node_feats, Wsu, Wvu);
    k_edge_mm<<<148, 256, SMEM_TC>>>(vectors, edge_feats, eidx, W1, W2);
    k_post<<<148, TB_C, SMEM_C_BYTES>>>(Wsp, Wvp, Ps1, Ps2, Ps3, Pvv,
                                        Pv1, Pv2, Pv3, Rw1, Rw2, Rg, Rvm, out);
}

// round 16
// speedup vs baseline: 1.3230x; 1.1165x over previous
#include <cuda_runtime.h>
#include <cuda_bf16.h>
#include <math.h>
#include <stdint.h>

#define NN 50000
#define EE 800000

extern __shared__ char dynsm[];

__device__ float g_pre[(size_t)NN * 64 * 4];
__device__ float g_acc[(size_t)NN * 64 * 4];

__device__ __forceinline__ float silu(float x) {
    return x * (1.0f / (1.0f + __expf(-x)));
}

// split a pair of floats into bf16 hi and lo packed u32s
__device__ __forceinline__ void split2(float a, float b, uint32_t& hi, uint32_t& lo) {
    __nv_bfloat16 ah = __float2bfloat16(a);
    __nv_bfloat16 bh = __float2bfloat16(b);
    __nv_bfloat16 al = __float2bfloat16(a - __bfloat162float(ah));
    __nv_bfloat16 bl = __float2bfloat16(b - __bfloat162float(bh));
    hi = ((uint32_t)__bfloat16_as_ushort(bh) << 16) | (uint32_t)__bfloat16_as_ushort(ah);
    lo = ((uint32_t)__bfloat16_as_ushort(bl) << 16) | (uint32_t)__bfloat16_as_ushort(al);
}

// m16n8k16 row.col bf16 -> f32 accum (baseline PTX, works on plain sm_103)
__device__ __forceinline__ void mma16816(float* d, const uint32_t* a, const uint32_t* b) {
    asm volatile("mma.sync.aligned.m16n8k16.row.col.f32.bf16.bf16.f32 "
                 "{%0,%1,%2,%3}, {%4,%5,%6,%7}, {%8,%9}, {%0,%1,%2,%3};"
                 : "+f"(d[0]), "+f"(d[1]), "+f"(d[2]), "+f"(d[3])
                 : "r"(a[0]), "r"(a[1]), "r"(a[2]), "r"(a[3]),
                   "r"(b[0]), "r"(b[1]));
}

#define APITCH 72   // bf16 elems per row (144 B) -> conflict-light fragment access

// A fragment: rows R+(l>>2), R+(l>>2)+8 ; k-cols k0+(l&3)*2 (+8)
__device__ __forceinline__ void lda_frag(uint32_t* a, const __nv_bfloat16* base,
                                         int R, int l, int k0) {
    int r = R + (l >> 2);
    int c = k0 + (l & 3) * 2;
    a[0] = *(const uint32_t*)(base + r * APITCH + c);
    a[1] = *(const uint32_t*)(base + (r + 8) * APITCH + c);
    a[2] = *(const uint32_t*)(base + r * APITCH + c + 8);
    a[3] = *(const uint32_t*)(base + (r + 8) * APITCH + c + 8);
}
// B fragment (col-major k x n): Wt stored [n][k]
__device__ __forceinline__ void ldb_frag(uint32_t* b, const __nv_bfloat16* base,
                                         int n0, int l, int k0) {
    int n = n0 + (l >> 2);
    int k = k0 + (l & 3) * 2;
    b[0] = *(const uint32_t*)(base + n * APITCH + k);
    b[1] = *(const uint32_t*)(base + n * APITCH + k + 8);
}

// ---------------------------------------------------------------------------
// Kernel A: node pre-transform + accumulator zeroing
// ---------------------------------------------------------------------------
__global__ void k_pre(const float* __restrict__ nf,
                      const float* __restrict__ Wsu,
                      const float* __restrict__ Wvu) {
    float* sm = (float*)dynsm;
    float* sWs  = sm;
    float* sWv  = sm + 4096;
    float* sRaw = sm + 8192;

    int tid = threadIdx.x;
    for (int i = tid; i < 4096; i += 256) { sWs[i] = Wsu[i]; sWv[i] = Wvu[i]; }

    int n0 = blockIdx.x * 32;
    for (int i = tid; i < 32 * 64; i += 256) {
        int nl = i >> 6, c4 = i & 63;
        int gn = n0 + nl;
        float4 v = make_float4(0.f, 0.f, 0.f, 0.f);
        if (gn < NN) v = ((const float4*)nf)[(size_t)gn * 64 + c4];
        ((float4*)(sRaw + nl * 256))[c4] = v;
    }
    __syncthreads();

    int kk = tid & 31;
    int g  = tid >> 5;
    int nbase = g * 4;

    float acc[4][2][4];
#pragma unroll
    for (int a = 0; a < 4; a++)
#pragma unroll
        for (int b = 0; b < 2; b++)
#pragma unroll
            for (int q = 0; q < 4; q++) acc[a][b][q] = 0.f;

    for (int c = 0; c < 64; c++) {
        float ws0 = sWs[c * 64 + kk], ws1 = sWs[c * 64 + kk + 32];
        float wv0 = sWv[c * 64 + kk], wv1 = sWv[c * 64 + kk + 32];
#pragma unroll
        for (int a = 0; a < 4; a++) {
            const float* row = sRaw + (nbase + a) * 256;
            float sv = row[c];
            float v0 = row[64 + c * 3 + 0];
            float v1 = row[64 + c * 3 + 1];
            float v2 = row[64 + c * 3 + 2];
            acc[a][0][0] += sv * ws0;  acc[a][1][0] += sv * ws1;
            acc[a][0][1] += v0 * wv0;  acc[a][1][1] += v0 * wv1;
            acc[a][0][2] += v1 * wv0;  acc[a][1][2] += v1 * wv1;
            acc[a][0][3] += v2 * wv0;  acc[a][1][3] += v2 * wv1;
        }
    }
#pragma unroll
    for (int a = 0; a < 4; a++) {
        int gn = n0 + nbase + a;
        if (gn >= NN) continue;
        ((float4*)g_pre)[(size_t)gn * 64 + kk] =
            make_float4(acc[a][0][0], acc[a][0][1], acc[a][0][2], acc[a][0][3]);
        ((float4*)g_pre)[(size_t)gn * 64 + kk + 32] =
            make_float4(acc[a][1][0], acc[a][1][1], acc[a][1][2], acc[a][1][3]);
        ((float4*)g_acc)[(size_t)gn * 64 + kk]      = make_float4(0.f, 0.f, 0.f, 0.f);
        ((float4*)g_acc)[(size_t)gn * 64 + kk + 32] = make_float4(0.f, 0.f, 0.f, 0.f);
    }
}

// ---------------------------------------------------------------------------
// Kernel B: edge kernel via mma.sync (HMMA). 12 warps (384 thr); 16 edges per
// warp-tile. R14 pipeline; +50% warps/SMSP for latency hiding.
// ---------------------------------------------------------------------------
#define NW    12
#define TB_B  (NW * 32)
#define O_W1H 0u
#define O_W1L 9216u
#define O_W2H 18432u
#define O_W2L 64512u
#define O_AHI 110592u                      // 192 rows * 144 B = 27648
#define O_ALO (O_AHI + 27648u)             // 138240
#define O_HHI (O_ALO + 27648u)             // 165888
#define O_HLO (O_HHI + 27648u)             // 193536
#define O_Y   (O_HLO + 27648u)             // 221184 (192*3*4 = 2304)
#define O_SND (O_Y + 2304u)                // 223488 (192*4)
#define O_RCV (O_SND + 768u)               // 224256
#define SMEM_TC (O_RCV + 768u)             // 225024

#define NGRP (EE / 16)   // 50000

__global__ void __launch_bounds__(TB_B, 1)
k_edge_mm(const float* __restrict__ vectors,
          const float* __restrict__ ef,
          const int* __restrict__ eidx,
          const float* __restrict__ W1,
          const float* __restrict__ W2) {
    char* sm = dynsm;
    __nv_bfloat16* W1H = (__nv_bfloat16*)(sm + O_W1H);
    __nv_bfloat16* W1L = (__nv_bfloat16*)(sm + O_W1L);
    __nv_bfloat16* W2H = (__nv_bfloat16*)(sm + O_W2H);
    __nv_bfloat16* W2L = (__nv_bfloat16*)(sm + O_W2L);
    __nv_bfloat16* AHI = (__nv_bfloat16*)(sm + O_AHI);
    __nv_bfloat16* ALO = (__nv_bfloat16*)(sm + O_ALO);
    __nv_bfloat16* HHI = (__nv_bfloat16*)(sm + O_HHI);
    __nv_bfloat16* HLO = (__nv_bfloat16*)(sm + O_HLO);
    float* sY   = (float*)(sm + O_Y);
    int*   sSnd = (int*)(sm + O_SND);
    int*   sRcv = (int*)(sm + O_RCV);

    int tid  = threadIdx.x;
    int warp = tid >> 5;
    int l    = tid & 31;

    // stage W1^T, W2^T (hi/lo) once
    for (int i = tid; i < 4096; i += TB_B) {
        int k = i >> 6, n = i & 63;
        float v = W1[i];
        __nv_bfloat16 vh = __float2bfloat16(v);
        W1H[n * APITCH + k] = vh;
        W1L[n * APITCH + k] = __float2bfloat16(v - __bfloat162float(vh));
    }
    for (int i = tid; i < 20480; i += TB_B) {
        int k = i / 320, j = i - k * 320;
        float v = W2[i];
        __nv_bfloat16 vh = __float2bfloat16(v);
        W2H[j * APITCH + k] = vh;
        W2L[j * APITCH + k] = __float2bfloat16(v - __bfloat162float(vh));
    }
    __syncthreads();

    const int* snd = eidx;
    const int* rcv = eidx + EE;
    int R = warp * 16;
    int gw = blockIdx.x * NW + warp;
    const int stride = 148 * NW;

    for (int grp = gw; grp < NGRP; grp += stride) {
        int e0 = grp * 16;

        // ---- stage 16 edges of EF, split hi/lo ----
        const float4* gsrc = (const float4*)(ef + (size_t)e0 * 64);
#pragma unroll
        for (int j = 0; j < 8; j++) {
            int idx4 = l + 32 * j;
            float4 f = gsrc[idx4];
            int idx = idx4 * 4;
            int e = idx >> 6, c = idx & 63;
            uint32_t h0, l0, h1, l1;
            split2(f.x, f.y, h0, l0);
            split2(f.z, f.w, h1, l1);
            *(uint2*)(AHI + (R + e) * APITCH + c) = make_uint2(h0, h1);
            *(uint2*)(ALO + (R + e) * APITCH + c) = make_uint2(l0, l1);
        }
        if (l < 16) {
            int ge = e0 + l;
            float vx = vectors[(size_t)ge * 3 + 0];
            float vy = vectors[(size_t)ge * 3 + 1];
            float vz = vectors[(size_t)ge * 3 + 2];
            float sc = 1.7320508075688772f /
                       (sqrtf(vx * vx + vy * vy + vz * vz) + 1e-12f);
            sY[(R + l) * 3 + 0] = vx * sc;
            sY[(R + l) * 3 + 1] = vy * sc;
            sY[(R + l) * 3 + 2] = vz * sc;
            sSnd[R + l] = snd[ge];
            sRcv[R + l] = rcv[ge];
        }
        __syncwarp();

        // ---- GEMM1: D1(16x64) = EF @ W1 (3-pass split) ----
        float d1[8][4];
#pragma unroll
        for (int n = 0; n < 8; n++)
#pragma unroll
            for (int q = 0; q < 4; q++) d1[n][q] = 0.f;
#pragma unroll
        for (int ks = 0; ks < 4; ks++) {
            int k0 = ks * 16;
            uint32_t ah[4], al[4];
            lda_frag(ah, AHI, R, l, k0);
            lda_frag(al, ALO, R, l, k0);
#pragma unroll
            for (int n = 0; n < 8; n++) {
                uint32_t bh[2], bl[2];
                ldb_frag(bh, W1H, n * 8, l, k0);
                ldb_frag(bl, W1L, n * 8, l, k0);
                mma16816(d1[n], ah, bh);
                mma16816(d1[n], ah, bl);
                mma16816(d1[n], al, bh);
            }
        }

        // ---- H = silu(D1), re-split into smem ----
        {
            int r = R + (l >> 2);
#pragma unroll
            for (int n = 0; n < 8; n++) {
                int c0 = n * 8 + (l & 3) * 2;
                uint32_t h, lo;
                split2(silu(d1[n][0]), silu(d1[n][1]), h, lo);
                *(uint32_t*)(HHI + r * APITCH + c0) = h;
                *(uint32_t*)(HLO + r * APITCH + c0) = lo;
                split2(silu(d1[n][2]), silu(d1[n][3]), h, lo);
                *(uint32_t*)(HHI + (r + 8) * APITCH + c0) = h;
                *(uint32_t*)(HLO + (r + 8) * APITCH + c0) = lo;
            }
        }
        __syncwarp();

        // ---- hoist epilogue invariants (per-thread edge rows) ----
        int eA = l >> 2, eB = eA + 8;
        int cc0 = (l & 3) * 2;
        int snA = sSnd[R + eA], rcA = sRcv[R + eA];
        int snB = sSnd[R + eB], rcB = sRcv[R + eB];
        float YxA = sY[(R + eA) * 3 + 0];
        float YyA = sY[(R + eA) * 3 + 1];
        float YzA = sY[(R + eA) * 3 + 2];
        float YxB = sY[(R + eB) * 3 + 0];
        float YyB = sY[(R + eB) * 3 + 1];
        float YzB = sY[(R + eB) * 3 + 2];
        const float4* prebA = ((const float4*)g_pre) + (size_t)snA * 64;
        const float4* prebB = ((const float4*)g_pre) + (size_t)snB * 64;
        float4* accbA = ((float4*)g_acc) + (size_t)rcA * 64;
        float4* accbB = ((float4*)g_acc) + (size_t)rcB * 64;

        // prime gather for n=0 (overlaps with fragment hoist below)
        float4 pA0 = prebA[cc0], pA1 = prebA[cc0 + 1];
        float4 pB0 = prebB[cc0], pB1 = prebB[cc0 + 1];

        // ---- hoist H fragments across the n loop ----
        uint32_t Ah[4][4], Al[4][4];
#pragma unroll
        for (int ks = 0; ks < 4; ks++) {
            lda_frag(Ah[ks], HHI, R, l, ks * 16);
            lda_frag(Al[ks], HLO, R, l, ks * 16);
        }

        // ---- GEMM2 per 8-channel block + pipelined epilogue ----
#pragma unroll 1
        for (int n = 0; n < 8; n++) {
            float d2[5][4];
#pragma unroll
            for (int j = 0; j < 5; j++)
#pragma unroll
                for (int q = 0; q < 4; q++) d2[j][q] = 0.f;
#pragma unroll
            for (int ks = 0; ks < 4; ks++) {
                int k0 = ks * 16;
#pragma unroll
                for (int j = 0; j < 5; j++) {
                    uint32_t bh[2], bl[2];
                    ldb_frag(bh, W2H, j * 64 + n * 8, l, k0);
                    ldb_frag(bl, W2L, j * 64 + n * 8, l, k0);
                    mma16816(d2[j], Ah[ks], bh);
                    mma16816(d2[j], Ah[ks], bl);
                    mma16816(d2[j], Al[ks], bh);
                }
            }

            // prefetch gather for n+1 (consumed after next block's MMA chain)
            float4 nA0, nA1, nB0, nB1;
            if (n < 7) {
                int cn = (n + 1) * 8 + cc0;
                nA0 = prebA[cn]; nA1 = prebA[cn + 1];
                nB0 = prebB[cn]; nB1 = prebB[cn + 1];
            }

            int c0 = n * 8 + cc0;
            // half 0: edge row eA, channels c0 / c0+1
            {
                float4 pr[2] = {pA0, pA1};
#pragma unroll
                for (int cc = 0; cc < 2; cc++) {
                    float w0 = d2[0][cc], w1 = d2[1][cc], w2 = d2[2][cc];
                    float w3 = d2[3][cc], w4 = d2[4][cc];
                    float sj = pr[cc].x, vx = pr[cc].y, vy = pr[cc].z, vz = pr[cc].w;
                    float vdY = vx * YxA + vy * YyA + vz * YzA;
                    float ms = w0 * sj + w1 * vdY;
                    float cx = vy * YzA - vz * YyA;
                    float cy = vz * YxA - vx * YzA;
                    float cz = vx * YyA - vy * YxA;
                    float t = w2 * sj;
                    float mvx = t * YxA + w3 * vx + w4 * cx;
                    float mvy = t * YyA + w3 * vy + w4 * cy;
                    float mvz = t * YzA + w3 * vz + w4 * cz;
                    float4* dst = accbA + (c0 + cc);
                    asm volatile("red.global.add.v4.f32 [%0], {%1,%2,%3,%4};"
                                 :: "l"(dst), "f"(ms), "f"(mvx), "f"(mvy), "f"(mvz)
                                 : "memory");
                }
            }
            // half 1: edge row eB, channels c0 / c0+1
            {
                float4 pr[2] = {pB0, pB1};
#pragma unroll
                for (int cc = 0; cc < 2; cc++) {
                    float w0 = d2[0][2 + cc], w1 = d2[1][2 + cc], w2 = d2[2][2 + cc];
                    float w3 = d2[3][2 + cc], w4 = d2[4][2 + cc];
                    float sj = pr[cc].x, vx = pr[cc].y, vy = pr[cc].z, vz = pr[cc].w;
                    float vdY = vx * YxB + vy * YyB + vz * YzB;
                    float ms = w0 * sj + w1 * vdY;
                    float cx = vy * YzB - vz * YyB;
                    float cy = vz * YxB - vx * YzB;
                    float cz = vx * YyB - vy * YxB;
                    float t = w2 * sj;
                    float mvx = t * YxB + w3 * vx + w4 * cx;
                    float mvy = t * YyB + w3 * vy + w4 * cy;
                    float mvz = t * YzB + w3 * vz + w4 * cz;
                    float4* dst = accbB + (c0 + cc);
                    asm volatile("red.global.add.v4.f32 [%0], {%1,%2,%3,%4};"
                                 :: "l"(dst), "f"(ms), "f"(mvx), "f"(mvy), "f"(mvz)
                                 : "memory");
                }
            }
            pA0 = nA0; pA1 = nA1; pB0 = nB0; pB1 = nB1;
        }
        __syncwarp();
    }
}

// ---------------------------------------------------------------------------
// Kernel C: node post (persistent) — unchanged (known-good)
// ---------------------------------------------------------------------------
#define NB   8
#define TB_C 512
#define NT_C (NN / NB)
#define SMEM_C_BYTES ((11 * 4096 + 64 + 64 + 512 + 1536 + 512 + 512 + 1536 + 512 + 512 + 32) * 4)

__global__ void k_post(const float* __restrict__ Wsp, const float* __restrict__ Wvp,
                       const float* __restrict__ Ps1w, const float* __restrict__ Ps2w,
                       const float* __restrict__ Ps3w, const float* __restrict__ Pvvw,
                       const float* __restrict__ Pv1w, const float* __restrict__ Pv2w,
                       const float* __restrict__ Pv3w, const float* __restrict__ Rw1,
                       const float* __restrict__ Rw2, const float* __restrict__ Rg,
                       const float* __restrict__ Rvm, float* __restrict__ out) {
    float* sm = (float*)dynsm;
    float* sWsp = sm + 0 * 4096;
    float* sWvp = sm + 1 * 4096;
    float* sPs1 = sm + 2 * 4096;
    float* sPs2 = sm + 3 * 4096;
    float* sPs3 = sm + 4 * 4096;
    float* sPvv = sm + 5 * 4096;
    float* sPv1 = sm + 6 * 4096;
    float* sPv2 = sm + 7 * 4096;
    float* sPv3 = sm + 8 * 4096;
    float* sRw1 = sm + 9 * 4096;
    float* sRw2 = sm + 10 * 4096;
    float* sRg  = sm + 11 * 4096;
    float* sRvm = sRg + 64;
    float* sRs  = sRvm + 64;
    float* sRv  = sRs + 512;
    float* sAs  = sRv + 1536;
    float* sVv  = sAs + 512;
    float* sAv  = sVv + 512;
    float* sPsb = sAv + 1536;
    float* sHr  = sPsb + 512;
    float* sVs  = sHr + 512;

    int tid = threadIdx.x;
    for (int i = tid; i < 4096; i += TB_C) {
        sWsp[i] = Wsp[i];  sWvp[i] = Wvp[i];
        sPs1[i] = Ps1w[i]; sPs2[i] = Ps2w[i]; sPs3[i] = Ps3w[i];
        sPvv[i] = Pvvw[i];
        sPv1[i] = Pv1w[i]; sPv2[i] = Pv2w[i]; sPv3[i] = Pv3w[i];
        sRw1[i] = Rw1[i];  sRw2[i] = Rw2[i];
    }
    if (tid < 64) { sRg[tid] = Rg[tid]; sRvm[tid] = Rvm[tid]; }

    int k = tid & 63;
    int g = tid >> 6;
    float* out_s  = out;
    float* out_v  = out + (size_t)NN * 64;
    float* out_nf = out + (size_t)NN * 67;

    for (int tile = blockIdx.x; tile < NT_C; tile += gridDim.x) {
        int gn = tile * NB + g;
        __syncthreads();

        float4 r4 = ((const float4*)g_acc)[(size_t)gn * 64 + k];
        const float inv = 1.0f / 16.0f;
        sRs[g * 64 + k] = r4.x * inv;
        sRv[(g * 64 + k) * 3 + 0] = r4.y * inv;
        sRv[(g * 64 + k) * 3 + 1] = r4.z * inv;
        sRv[(g * 64 + k) * 3 + 2] = r4.w * inv;
        __syncthreads();

        float as = 0.f, av0 = 0.f, av1 = 0.f, av2 = 0.f;
        for (int c = 0; c < 64; c++) {
            float wsp = sWsp[c * 64 + k];
            float wvp = sWvp[c * 64 + k];
            float rs = sRs[g * 64 + c];
            float r0 = sRv[(g * 64 + c) * 3 + 0];
            float r1 = sRv[(g * 64 + c) * 3 + 1];
            float r2 = sRv[(g * 64 + c) * 3 + 2];
            as += rs * wsp; av0 += r0 * wvp; av1 += r1 * wvp; av2 += r2 * wvp;
        }
        sAs[g * 64 + k] = as;
        sAv[(g * 64 + k) * 3 + 0] = av0;
        sAv[(g * 64 + k) * 3 + 1] = av1;
        sAv[(g * 64 + k) * 3 + 2] = av2;
        sVv[g * 64 + k] = av0 * av0 + av1 * av1 + av2 * av2;
        __syncthreads();

        float ps = 0.f, pv0 = 0.f, pv1 = 0.f, pv2 = 0.f;
        for (int c = 0; c < 64; c++) {
            float a = sAs[g * 64 + c];
            float a2 = a * a;
            float a3 = a2 * a;
            float vvc = sVv[g * 64 + c];
            ps += a * sPs1[c * 64 + k] + a2 * sPs2[c * 64 + k]
                + a3 * sPs3[c * 64 + k] + vvc * sPvv[c * 64 + k];
            float q = sPv1[c * 64 + k] + a * sPv2[c * 64 + k] + a2 * sPv3[c * 64 + k];
            pv0 += sAv[(g * 64 + c) * 3 + 0] * q;
            pv1 += sAv[(g * 64 + c) * 3 + 1] * q;
            pv2 += sAv[(g * 64 + c) * 3 + 2] * q;
        }
        sPsb[g * 64 + k] = ps;
        float rv = sRvm[k];
        sRv[(g * 64 + k) * 3 + 0] = pv0 * rv;
        sRv[(g * 64 + k) * 3 + 1] = pv1 * rv;
        sRv[(g * 64 + k) * 3 + 2] = pv2 * rv;
        out_nf[(size_t)gn * 256 + k] = ps;
        out_nf[(size_t)gn * 256 + 64 + k * 3 + 0] = pv0;
        out_nf[(size_t)gn * 256 + 64 + k * 3 + 1] = pv1;
        out_nf[(size_t)gn * 256 + 64 + k * 3 + 2] = pv2;
        __syncthreads();

        float hr = 0.f;
        for (int c = 0; c < 64; c++) hr += sPsb[g * 64 + c] * sRw1[c * 64 + k];
        hr = silu(hr);
        sHr[g * 64 + k] = hr;
        if (k < 3) {
            float s = 0.f;
            for (int c = 0; c < 64; c++) s += sRv[(g * 64 + c) * 3 + k];
            sVs[g * 4 + k] = s;
        }
        __syncthreads();

        float os = 0.f, gs = 0.f;
        for (int m = 0; m < 64; m++) {
            float h = sHr[g * 64 + m];
            os += h * sRw2[m * 64 + k];
            gs += h * sRg[m];
        }
        out_s[(size_t)gn * 64 + k] = os;
        float gate = silu(gs);
        if (k < 3) out_v[(size_t)gn * 3 + k] = sVs[g * 4 + k] * gate;
    }
}

// ---------------------------------------------------------------------------
extern "C" void kernel_launch(void* const* d_in, const int* in_sizes, int n_in,
                              void* d_out, int out_size) {
    const float* vectors    = (const float*)d_in[0];
    const float* node_feats = (const float*)d_in[2];
    const float* edge_feats = (const float*)d_in[3];
    const int*   eidx       = (const int*)d_in[4];
    const float* Wsu        = (const float*)d_in[5];
    const float* Wvu        = (const float*)d_in[6];
    const float* W1         = (const float*)d_in[7];
    const float* W2         = (const float*)d_in[8];
    const float* Wsp        = (const float*)d_in[9];
    const float* Wvp        = (const float*)d_in[10];
    const float* Ps1        = (const float*)d_in[11];
    const float* Ps2        = (const float*)d_in[12];
    const float* Ps3        = (const float*)d_in[13];
    const float* Pvv        = (const float*)d_in[14];
    const float* Pv1        = (const float*)d_in[15];
    const float* Pv2        = (const float*)d_in[16];
    const float* Pv3        = (const float*)d_in[17];
    const float* Rw1        = (const float*)d_in[18];
    const float* Rw2        = (const float*)d_in[19];
    const float* Rg         = (const float*)d_in[20];
    const float* Rvm        = (const float*)d_in[21];
    float* out = (float*)d_out;

    const int SMEM_A_BYTES = (4096 + 4096 + 32 * 256) * 4;
    cudaFuncSetAttribute(k_pre,     cudaFuncAttributeMaxDynamicSharedMemorySize, SMEM_A_BYTES);
    cudaFuncSetAttribute(k_edge_mm, cudaFuncAttributeMaxDynamicSharedMemorySize, SMEM_TC);
    cudaFuncSetAttribute(k_post,    cudaFuncAttributeMaxDynamicSharedMemorySize, SMEM_C_BYTES);

    k_pre<<<(NN + 31) / 32, 256, SMEM_A_BYTES>>>(node_feats, Wsu, Wvu);
    k_edge_mm<<<148, TB_B, SMEM_TC>>>(vectors, edge_feats, eidx, W1, W2);
    k_post<<<148, TB_C, SMEM_C_BYTES>>>(Wsp, Wvp, Ps1, Ps2, Ps3, Pvv,
                                        Pv1, Pv2, Pv3, Rw1, Rw2, Rg, Rvm, out);
}